// round 15
// baseline (speedup 1.0000x reference)
#include <cuda_runtime.h>
#include <cuda_bf16.h>

// PositionalEncoding: out[p][j] = X[p][j] + (j even ? sin(p*w_j) : cos(p*w_j))
//   w_j = 10000^{-(j + (j%2))/n},  n = 4096, m = 8192 rows.
//
// R15: final point on the register-resident batching axis discovered in
// R13/R14 (deep per-thread MLP at low occupancy == fastest). ROWS=32 fully
// batch-loaded: 32 LDG.128 in flight per thread (~150 regs, occ ~19%),
// grid (8,256)=2048 CTAs. Halves prologue cost per byte vs R14.
// 3-state shared-frequency angle-addition recurrence (drift ~3e-5 over 32
// steps, well under the 1e-3 threshold).

#define PE_M     8192
#define PE_N     4096
#define PE_NV4   (PE_N / 4)      // 1024 float4 per row
#define PE_ROWS  32              // rows per thread (all batch-loaded)
#define PE_TPB   128             // threads per block (column-quads)

__global__ __launch_bounds__(PE_TPB)
void pe_kernel(const float4* __restrict__ X, float4* __restrict__ Out) {
    const int cv   = blockIdx.x * PE_TPB + threadIdx.x;  // column-quad index, 0..1023
    const int row0 = blockIdx.y * PE_ROWS;

    const float L2_10K = 13.287712379549449f;  // log2(10000)

    // 3 distinct frequencies per quad: exponents (4cv + 2t)/n, t = 0,1,2
    float s[3], c[3], sw[3], cw[3];
#pragma unroll
    for (int t = 0; t < 3; t++) {
        const float e = (float)(4 * cv + 2 * t) * (1.0f / (float)PE_N);
        const float w = exp2f(-e * L2_10K);           // 10000^{-e}
        sincosf((float)row0 * w, &s[t], &c[t]);       // precise: angle up to ~8191
        __sincosf(w, &sw[t], &cw[t]);                 // fast: w in (0, 1]
    }

    const float4* __restrict__ xp = X   + (size_t)row0 * PE_NV4 + cv;
    float4*       __restrict__ yp = Out + (size_t)row0 * PE_NV4 + cv;

    // Batch all 32 loads — register-resident, maximal per-thread MLP.
    float4 v[PE_ROWS];
#pragma unroll
    for (int r = 0; r < PE_ROWS; r++)
        v[r] = __ldcs(xp + (size_t)r * PE_NV4);

    // Add table values; advance rotation per row.
    // cols 4cv+{0,1,2,3}: sin(w0), cos(w1), sin(w1), cos(w2)
#pragma unroll
    for (int r = 0; r < PE_ROWS; r++) {
        v[r].x += s[0];
        v[r].y += c[1];
        v[r].z += s[1];
        v[r].w += c[2];
#pragma unroll
        for (int t = 0; t < 3; t++) {
            const float ns = fmaf(s[t], cw[t],  c[t] * sw[t]);
            const float nc = fmaf(c[t], cw[t], -s[t] * sw[t]);
            s[t] = ns; c[t] = nc;
        }
    }

    // Streaming stores (write-once, evict-first).
#pragma unroll
    for (int r = 0; r < PE_ROWS; r++)
        __stcs(yp + (size_t)r * PE_NV4, v[r]);
}

extern "C" void kernel_launch(void* const* d_in, const int* in_sizes, int n_in,
                              void* d_out, int out_size) {
    (void)in_sizes; (void)n_in; (void)out_size;
    const float4* X   = (const float4*)d_in[0];
    float4*       Out = (float4*)d_out;

    dim3 block(PE_TPB);
    dim3 grid(PE_NV4 / PE_TPB, PE_M / PE_ROWS);   // (8, 256) = 2048 CTAs
    pe_kernel<<<grid, block>>>(X, Out);
}

// round 16
// speedup vs baseline: 1.0508x; 1.0508x over previous
#include <cuda_runtime.h>
#include <cuda_bf16.h>

// PositionalEncoding: out[p][j] = X[p][j] + (j even ? sin(p*w_j) : cos(p*w_j))
//   w_j = 10000^{-(j + (j%2))/n},  n = 4096, m = 8192 rows.
//
// FINAL (== R14, the measured optimum over 15 rounds):
//  * Transcendentals amortized via angle-addition recurrence along rows:
//      s' = s*cw + c*sw,  c' = c*cw - s*sw
//    with shared-frequency compression: cols 4cv+{0,1,2,3} have exponents
//    (4cv+{0,2,2,4})/n -> 3 distinct frequencies -> 3 states/thread,
//    6 sincos per 64 elements. fp32 drift over 16 steps ~1e-6.
//  * Register-resident load batching: ROWS=16 float4 loads held live
//    (regs=96, 16 LDG.128 in flight per thread). Measured knee of the
//    MLP-vs-occupancy curve: occ 26%/MLP16 (36.3us) beats occ 41%/MLP8
//    (36.5us) and occ 16%/MLP32 (39.2us).
//  * Streaming loads/stores (zero reuse); L2 policy tricks measured neutral.
//  * At the mixed read/write HBM ceiling: ~7.4 TB/s app-effective (~92% of
//    8 TB/s spec), DRAM 74% on cold-cache ncu.

#define PE_M     8192
#define PE_N     4096
#define PE_NV4   (PE_N / 4)      // 1024 float4 per row
#define PE_ROWS  16              // rows per thread (all batch-loaded)
#define PE_TPB   128             // threads per block (column-quads)

__global__ __launch_bounds__(PE_TPB)
void pe_kernel(const float4* __restrict__ X, float4* __restrict__ Out) {
    const int cv   = blockIdx.x * PE_TPB + threadIdx.x;  // column-quad index, 0..1023
    const int row0 = blockIdx.y * PE_ROWS;

    const float L2_10K = 13.287712379549449f;  // log2(10000)

    // 3 distinct frequencies per quad: exponents (4cv + 2t)/n, t = 0,1,2
    float s[3], c[3], sw[3], cw[3];
#pragma unroll
    for (int t = 0; t < 3; t++) {
        const float e = (float)(4 * cv + 2 * t) * (1.0f / (float)PE_N);
        const float w = exp2f(-e * L2_10K);           // 10000^{-e}
        sincosf((float)row0 * w, &s[t], &c[t]);       // precise: angle up to ~8191
        __sincosf(w, &sw[t], &cw[t]);                 // fast: w in (0, 1]
    }

    const float4* __restrict__ xp = X   + (size_t)row0 * PE_NV4 + cv;
    float4*       __restrict__ yp = Out + (size_t)row0 * PE_NV4 + cv;

    // Batch all 16 loads — register-resident, maximal useful per-thread MLP.
    float4 v[PE_ROWS];
#pragma unroll
    for (int r = 0; r < PE_ROWS; r++)
        v[r] = __ldcs(xp + (size_t)r * PE_NV4);

    // Add table values; advance rotation per row.
    // cols 4cv+{0,1,2,3}: sin(w0), cos(w1), sin(w1), cos(w2)
#pragma unroll
    for (int r = 0; r < PE_ROWS; r++) {
        v[r].x += s[0];
        v[r].y += c[1];
        v[r].z += s[1];
        v[r].w += c[2];
#pragma unroll
        for (int t = 0; t < 3; t++) {
            const float ns = fmaf(s[t], cw[t],  c[t] * sw[t]);
            const float nc = fmaf(c[t], cw[t], -s[t] * sw[t]);
            s[t] = ns; c[t] = nc;
        }
    }

    // Streaming stores (write-once, evict-first).
#pragma unroll
    for (int r = 0; r < PE_ROWS; r++)
        __stcs(yp + (size_t)r * PE_NV4, v[r]);
}

extern "C" void kernel_launch(void* const* d_in, const int* in_sizes, int n_in,
                              void* d_out, int out_size) {
    (void)in_sizes; (void)n_in; (void)out_size;
    const float4* X   = (const float4*)d_in[0];
    float4*       Out = (float4*)d_out;

    dim3 block(PE_TPB);
    dim3 grid(PE_NV4 / PE_TPB, PE_M / PE_ROWS);   // (8, 512) = 4096 CTAs
    pe_kernel<<<grid, block>>>(X, Out);
}